// round 3
// baseline (speedup 1.0000x reference)
#include <cuda_runtime.h>
#include <cstdint>
#include <cstddef>

// ---------------- problem constants ----------------
constexpr int BN_  = 32;    // batch
constexpr int CC   = 384;   // channels
constexpr int HH   = 32, WW = 32, HW = 1024;
constexpr int HK   = 16, WK = 16, HWK = 256;
constexpr int INNER = 384;  // heads*dim
constexpr int HEADS = 6, DH = 64;
constexpr float SCALE = 0.125f;   // 64^-0.5
constexpr float EPS = 1e-5f;

// ---------------- scratch (device globals; no runtime alloc) ----------------
__device__ float g_tq [(size_t)BN_*CC*HW];        // dwbn(q) output, [b][c][p] (col-major A)
__device__ float g_tkv[(size_t)BN_*CC*HWK];       // dwbn(kv) output
__device__ float g_q  [(size_t)BN_*HW*INNER];     // q, row-major [b*HW+p][inner]
__device__ float g_kv [(size_t)BN_*HWK*2*INNER];  // kv, row-major [b*256+j][768]
__device__ float g_ao [(size_t)BN_*HW*INNER];     // attention out, row-major

// ---------------- depthwise 3x3 conv + BN ----------------
template<int STRIDE, int HO, int WO, int CPB>
__global__ void dwbn_kernel(const float* __restrict__ x, const float* __restrict__ dw,
                            const float* __restrict__ gamma, const float* __restrict__ beta,
                            const float* __restrict__ mean, const float* __restrict__ var,
                            float* __restrict__ out)
{
    const int tid = threadIdx.x;
    const int xo = tid % WO;
    const int cl = tid / WO;
    const int yo = blockIdx.x;
    const int c  = blockIdx.y * CPB + cl;
    const int b  = blockIdx.z;

    const float* xp = x + (size_t)(b*CC + c) * (HH*WW);
    const float* wp = dw + c*9;

    const int yc = yo * STRIDE, xc = xo * STRIDE;
    float s = 0.f;
#pragma unroll
    for (int dy = -1; dy <= 1; dy++) {
        int yy = yc + dy;
        if (yy < 0 || yy >= HH) continue;
#pragma unroll
        for (int dx = -1; dx <= 1; dx++) {
            int xx = xc + dx;
            if (xx < 0 || xx >= WW) continue;
            s += xp[yy*WW + xx] * wp[(dy+1)*3 + (dx+1)];
        }
    }
    float inv = gamma[c] * rsqrtf(var[c] + EPS);
    float val = s * inv + (beta[c] - mean[c]*inv);
    out[(size_t)(b*CC + c) * (HO*WO) + yo*WO + xo] = val;
}

// ---------------- tiled SGEMM ----------------
// Out[m][n] = sum_k A(m,k) * Wt[n*K + k]   (Wt row-major [N][K])
// ACOL:  A(m,k) = A[b*K*Mper + k*Mper + p]  with m = b*Mper + p   (per-batch col-major)
// !ACOL: A(m,k) = A[m*K + k]                                      (global row-major)
// TOUT:  store transposed: Out[(b*N + n)*Mper + p]  (+ bias[n] if BIAS)
template<bool ACOL, bool TOUT, bool BIAS>
__global__ void __launch_bounds__(256) gemm128(const float* __restrict__ A,
                                               const float* __restrict__ Wt,
                                               const float* __restrict__ bias,
                                               float* __restrict__ Out,
                                               int Mper, int K, int N)
{
    constexpr int BM = 128, BNt = 128, BK = 8;
    __shared__ float As[2][BK][BM];
    __shared__ float Bs[2][BK][BNt];

    const int tid = threadIdx.x;
    const int m0  = blockIdx.x * BM;
    const int n0  = blockIdx.y * BNt;
    const int b   = m0 / Mper;      // tiles never straddle batches (Mper % 128 == 0)
    const int p0  = m0 % Mper;

    const float* Abase = ACOL ? (A + (size_t)b*K*Mper + p0)
                              : (A + (size_t)m0 * K);

    const int a_kk = tid >> 5, a_i4 = tid & 31;   // ACOL load map
    const int a_i  = tid >> 1, a_kq = tid & 1;    // row-major load map
    const int b_n  = tid >> 1, b_kq = tid & 1;

    const int rm = tid >> 4;   // 0..15 (row group)
    const int cn = tid & 15;   // 0..15 (col group)

    float acc[8][8];
#pragma unroll
    for (int i = 0; i < 8; i++)
#pragma unroll
        for (int j = 0; j < 8; j++) acc[i][j] = 0.f;

    float4 ra, rb;
    auto loadG = [&](int k0) {
        if (ACOL) ra = *(const float4*)(Abase + (size_t)(k0 + a_kk)*Mper + a_i4*4);
        else      ra = *(const float4*)(Abase + (size_t)a_i*K + k0 + a_kq*4);
        rb = *(const float4*)(Wt + (size_t)(n0 + b_n)*K + k0 + b_kq*4);
    };
    auto storeS = [&](int buf) {
        if (ACOL) {
            *(float4*)&As[buf][a_kk][a_i4*4] = ra;
        } else {
            As[buf][a_kq*4+0][a_i] = ra.x;
            As[buf][a_kq*4+1][a_i] = ra.y;
            As[buf][a_kq*4+2][a_i] = ra.z;
            As[buf][a_kq*4+3][a_i] = ra.w;
        }
        Bs[buf][b_kq*4+0][b_n] = rb.x;
        Bs[buf][b_kq*4+1][b_n] = rb.y;
        Bs[buf][b_kq*4+2][b_n] = rb.z;
        Bs[buf][b_kq*4+3][b_n] = rb.w;
    };

    const int T = K / BK;
    loadG(0);
    storeS(0);
    __syncthreads();

    for (int t = 0; t < T; t++) {
        const int buf = t & 1;
        if (t + 1 < T) loadG((t + 1) * BK);
#pragma unroll
        for (int kk = 0; kk < BK; kk++) {
            float a[8], w[8];
            *(float4*)&a[0] = *(const float4*)&As[buf][kk][rm*8];
            *(float4*)&a[4] = *(const float4*)&As[buf][kk][rm*8 + 4];
            *(float4*)&w[0] = *(const float4*)&Bs[buf][kk][cn*8];
            *(float4*)&w[4] = *(const float4*)&Bs[buf][kk][cn*8 + 4];
#pragma unroll
            for (int i = 0; i < 8; i++)
#pragma unroll
                for (int j = 0; j < 8; j++)
                    acc[i][j] += a[i] * w[j];
        }
        if (t + 1 < T) storeS(buf ^ 1);
        __syncthreads();
    }

    if (!TOUT) {
#pragma unroll
        for (int i = 0; i < 8; i++) {
            float* dst = Out + (size_t)(m0 + rm*8 + i)*N + n0 + cn*8;
            float4 v0 = {acc[i][0], acc[i][1], acc[i][2], acc[i][3]};
            float4 v1 = {acc[i][4], acc[i][5], acc[i][6], acc[i][7]};
            *(float4*)dst       = v0;
            *((float4*)dst + 1) = v1;
        }
    } else {
#pragma unroll
        for (int j = 0; j < 8; j++) {
            int n = n0 + cn*8 + j;
            float bv = BIAS ? bias[n] : 0.f;
            float* dst = Out + ((size_t)b*N + n)*Mper + p0 + rm*8;
            float4 v0 = {acc[0][j]+bv, acc[1][j]+bv, acc[2][j]+bv, acc[3][j]+bv};
            float4 v1 = {acc[4][j]+bv, acc[5][j]+bv, acc[6][j]+bv, acc[7][j]+bv};
            *(float4*)dst       = v0;
            *((float4*)dst + 1) = v1;
        }
    }
}

// ---------------- attention (flash-style, fp32) ----------------
// Per block: 128 q-rows of one (b,h). K/V streamed in 64-row chunks through smem.
__global__ void __launch_bounds__(128) attn_kernel(const float* __restrict__ Q,
                                                   const float* __restrict__ KV,
                                                   float* __restrict__ AO)
{
    const int b = blockIdx.z, h = blockIdx.y;
    const int p = blockIdx.x * 128 + threadIdx.x;

    __shared__ float Ks[64][64];
    __shared__ float Vs[64][64];

    const float* qp = Q + ((size_t)(b*HW + p)*INNER + h*DH);
    float4 qv[16];
#pragma unroll
    for (int i = 0; i < 16; i++) {
        float4 v = *(const float4*)(qp + i*4);
        v.x *= SCALE; v.y *= SCALE; v.z *= SCALE; v.w *= SCALE;
        qv[i] = v;
    }

    float m = -1e30f, l = 0.f;
    float4 acc[16];
#pragma unroll
    for (int i = 0; i < 16; i++) acc[i] = make_float4(0.f, 0.f, 0.f, 0.f);

    const float* kvb = KV + (size_t)(b*HWK)*(2*INNER) + h*DH;

    for (int ch = 0; ch < 4; ch++) {
        __syncthreads();
#pragma unroll
        for (int r = 0; r < 8; r++) {
            int idx = threadIdx.x + 128*r;       // 0..1023 float4 slots
            int jj = idx >> 4;
            int d4 = idx & 15;
            const float* src = kvb + (size_t)(ch*64 + jj)*(2*INNER) + d4*4;
            *(float4*)&Ks[jj][d4*4] = *(const float4*)src;
            *(float4*)&Vs[jj][d4*4] = *(const float4*)(src + INNER);
        }
        __syncthreads();

        for (int jj = 0; jj < 64; jj++) {
            float4 s4 = make_float4(0.f, 0.f, 0.f, 0.f);
#pragma unroll
            for (int i = 0; i < 16; i++) {
                float4 k4 = *(const float4*)&Ks[jj][i*4];
                s4.x += qv[i].x * k4.x;
                s4.y += qv[i].y * k4.y;
                s4.z += qv[i].z * k4.z;
                s4.w += qv[i].w * k4.w;
            }
            float s = (s4.x + s4.y) + (s4.z + s4.w);

            if (s > m) {   // rare rescale
                float ef = __expf(m - s);
                l *= ef;
#pragma unroll
                for (int i = 0; i < 16; i++) {
                    acc[i].x *= ef; acc[i].y *= ef; acc[i].z *= ef; acc[i].w *= ef;
                }
                m = s;
            }
            float es = __expf(s - m);
            l += es;
#pragma unroll
            for (int i = 0; i < 16; i++) {
                float4 v4 = *(const float4*)&Vs[jj][i*4];
                acc[i].x += es * v4.x;
                acc[i].y += es * v4.y;
                acc[i].z += es * v4.z;
                acc[i].w += es * v4.w;
            }
        }
    }

    float inv = 1.f / l;
    float* op = AO + ((size_t)(b*HW + p)*INNER + h*DH);
#pragma unroll
    for (int i = 0; i < 16; i++) {
        float4 v = acc[i];
        v.x *= inv; v.y *= inv; v.z *= inv; v.w *= inv;
        *(float4*)(op + i*4) = v;
    }
}

// ---------------- launch ----------------
extern "C" void kernel_launch(void* const* d_in, const int* in_sizes, int n_in,
                              void* d_out, int out_size)
{
    const float* x        = (const float*)d_in[0];
    const float* q_dw     = (const float*)d_in[1];
    const float* q_gamma  = (const float*)d_in[2];
    const float* q_beta   = (const float*)d_in[3];
    const float* q_mean   = (const float*)d_in[4];
    const float* q_var    = (const float*)d_in[5];
    const float* q_pw     = (const float*)d_in[6];
    const float* kv_dw    = (const float*)d_in[7];
    const float* kv_gamma = (const float*)d_in[8];
    const float* kv_beta  = (const float*)d_in[9];
    const float* kv_mean  = (const float*)d_in[10];
    const float* kv_var   = (const float*)d_in[11];
    const float* kv_pw    = (const float*)d_in[12];
    const float* out_w    = (const float*)d_in[13];
    const float* out_b    = (const float*)d_in[14];
    float* out = (float*)d_out;

    float *tq, *tkv, *qb, *kvb, *ao;
    cudaGetSymbolAddress((void**)&tq,  g_tq);
    cudaGetSymbolAddress((void**)&tkv, g_tkv);
    cudaGetSymbolAddress((void**)&qb,  g_q);
    cudaGetSymbolAddress((void**)&kvb, g_kv);
    cudaGetSymbolAddress((void**)&ao,  g_ao);

    // 1) depthwise+BN paths
    dwbn_kernel<1, HH, WW, 8> <<<dim3(HH, CC/8,  BN_), 256>>>(x, q_dw,  q_gamma,  q_beta,  q_mean,  q_var,  tq);
    dwbn_kernel<2, HK, WK, 16><<<dim3(HK, CC/16, BN_), 256>>>(x, kv_dw, kv_gamma, kv_beta, kv_mean, kv_var, tkv);

    // 2) pointwise GEMMs
    gemm128<true,  false, false><<<dim3(BN_*HW /128, INNER     /128), 256>>>(tq,  q_pw,  nullptr, qb,  HW,  CC, INNER);
    gemm128<true,  false, false><<<dim3(BN_*HWK/128, (2*INNER) /128), 256>>>(tkv, kv_pw, nullptr, kvb, HWK, CC, 2*INNER);

    // 3) attention
    attn_kernel<<<dim3(HW/128, HEADS, BN_), 128>>>(qb, kvb, ao);

    // 4) final projection (transposed store back to NCHW + bias)
    gemm128<false, true,  true ><<<dim3(BN_*HW/128, CC/128), 256>>>(ao, out_w, out_b, out, HW, INNER, CC);
}

// round 4
// speedup vs baseline: 1.0515x; 1.0515x over previous
#include <cuda_runtime.h>
#include <cstdint>
#include <cstddef>

// ---------------- problem constants ----------------
constexpr int BN_  = 32;    // batch
constexpr int CC   = 384;   // channels
constexpr int HH   = 32, WW = 32, HW = 1024;
constexpr int HK   = 16, WK = 16, HWK = 256;
constexpr int INNER = 384;  // heads*dim
constexpr int HEADS = 6, DH = 64;
constexpr float SCALE = 0.125f;   // 64^-0.5
constexpr float EPS = 1e-5f;

// ---------------- scratch (device globals; no runtime alloc) ----------------
__device__ float g_tq [(size_t)BN_*CC*HW];        // dwbn(q) output, [b][c][p] (col-major A)
__device__ float g_tkv[(size_t)BN_*CC*HWK];       // dwbn(kv) output
__device__ float g_q  [(size_t)BN_*HW*INNER];     // q, row-major [b*HW+p][inner]
__device__ float g_kv [(size_t)BN_*HWK*2*INNER];  // kv, row-major [b*256+j][768]
__device__ float g_ao [(size_t)BN_*HW*INNER];     // attention out, row-major

// ---------------- depthwise 3x3 conv + BN ----------------
template<int STRIDE, int HO, int WO, int CPB>
__global__ void dwbn_kernel(const float* __restrict__ x, const float* __restrict__ dw,
                            const float* __restrict__ gamma, const float* __restrict__ beta,
                            const float* __restrict__ mean, const float* __restrict__ var,
                            float* __restrict__ out)
{
    const int tid = threadIdx.x;
    const int xo = tid % WO;
    const int cl = tid / WO;
    const int yo = blockIdx.x;
    const int c  = blockIdx.y * CPB + cl;
    const int b  = blockIdx.z;

    const float* xp = x + (size_t)(b*CC + c) * (HH*WW);
    const float* wp = dw + c*9;

    const int yc = yo * STRIDE, xc = xo * STRIDE;
    float s = 0.f;
#pragma unroll
    for (int dy = -1; dy <= 1; dy++) {
        int yy = yc + dy;
        if (yy < 0 || yy >= HH) continue;
#pragma unroll
        for (int dx = -1; dx <= 1; dx++) {
            int xx = xc + dx;
            if (xx < 0 || xx >= WW) continue;
            s += xp[yy*WW + xx] * wp[(dy+1)*3 + (dx+1)];
        }
    }
    float inv = gamma[c] * rsqrtf(var[c] + EPS);
    float val = s * inv + (beta[c] - mean[c]*inv);
    out[(size_t)(b*CC + c) * (HO*WO) + yo*WO + xo] = val;
}

// ---------------- tiled SGEMM ----------------
// Out[m][n] = sum_k A(m,k) * Wt[n*K + k]   (Wt row-major [N][K])
// ACOL:  A(m,k) = A[b*K*Mper + k*Mper + p]  with m = b*Mper + p   (per-batch col-major)
// !ACOL: A(m,k) = A[m*K + k]                                      (global row-major)
// TOUT:  store transposed: Out[(b*N + n)*Mper + p]  (+ bias[n] if BIAS)
template<bool ACOL, bool TOUT, bool BIAS>
__global__ void __launch_bounds__(256) gemm128(const float* __restrict__ A,
                                               const float* __restrict__ Wt,
                                               const float* __restrict__ bias,
                                               float* __restrict__ Out,
                                               int Mper, int K, int N)
{
    constexpr int BM = 128, BNt = 128, BK = 8;
    __shared__ float As[2][BK][BM];
    __shared__ float Bs[2][BK][BNt];

    const int tid = threadIdx.x;
    const int m0  = blockIdx.x * BM;
    const int n0  = blockIdx.y * BNt;
    const int b   = m0 / Mper;      // tiles never straddle batches (Mper % 128 == 0)
    const int p0  = m0 % Mper;

    const float* Abase = ACOL ? (A + (size_t)b*K*Mper + p0)
                              : (A + (size_t)m0 * K);

    const int a_kk = tid >> 5, a_i4 = tid & 31;   // ACOL load map
    const int a_i  = tid >> 1, a_kq = tid & 1;    // row-major load map
    const int b_n  = tid >> 1, b_kq = tid & 1;

    const int rm = tid >> 4;   // 0..15 (row group)
    const int cn = tid & 15;   // 0..15 (col group)

    float acc[8][8];
#pragma unroll
    for (int i = 0; i < 8; i++)
#pragma unroll
        for (int j = 0; j < 8; j++) acc[i][j] = 0.f;

    float4 ra, rb;
    auto loadG = [&](int k0) {
        if (ACOL) ra = *(const float4*)(Abase + (size_t)(k0 + a_kk)*Mper + a_i4*4);
        else      ra = *(const float4*)(Abase + (size_t)a_i*K + k0 + a_kq*4);
        rb = *(const float4*)(Wt + (size_t)(n0 + b_n)*K + k0 + b_kq*4);
    };
    auto storeS = [&](int buf) {
        if (ACOL) {
            *(float4*)&As[buf][a_kk][a_i4*4] = ra;
        } else {
            As[buf][a_kq*4+0][a_i] = ra.x;
            As[buf][a_kq*4+1][a_i] = ra.y;
            As[buf][a_kq*4+2][a_i] = ra.z;
            As[buf][a_kq*4+3][a_i] = ra.w;
        }
        Bs[buf][b_kq*4+0][b_n] = rb.x;
        Bs[buf][b_kq*4+1][b_n] = rb.y;
        Bs[buf][b_kq*4+2][b_n] = rb.z;
        Bs[buf][b_kq*4+3][b_n] = rb.w;
    };

    const int T = K / BK;
    loadG(0);
    storeS(0);
    __syncthreads();

    for (int t = 0; t < T; t++) {
        const int buf = t & 1;
        if (t + 1 < T) loadG((t + 1) * BK);
#pragma unroll
        for (int kk = 0; kk < BK; kk++) {
            float a[8], w[8];
            *(float4*)&a[0] = *(const float4*)&As[buf][kk][rm*8];
            *(float4*)&a[4] = *(const float4*)&As[buf][kk][rm*8 + 4];
            *(float4*)&w[0] = *(const float4*)&Bs[buf][kk][cn*8];
            *(float4*)&w[4] = *(const float4*)&Bs[buf][kk][cn*8 + 4];
#pragma unroll
            for (int i = 0; i < 8; i++)
#pragma unroll
                for (int j = 0; j < 8; j++)
                    acc[i][j] += a[i] * w[j];
        }
        if (t + 1 < T) storeS(buf ^ 1);
        __syncthreads();
    }

    if (!TOUT) {
#pragma unroll
        for (int i = 0; i < 8; i++) {
            float* dst = Out + (size_t)(m0 + rm*8 + i)*N + n0 + cn*8;
            float4 v0 = {acc[i][0], acc[i][1], acc[i][2], acc[i][3]};
            float4 v1 = {acc[i][4], acc[i][5], acc[i][6], acc[i][7]};
            *(float4*)dst       = v0;
            *((float4*)dst + 1) = v1;
        }
    } else {
#pragma unroll
        for (int j = 0; j < 8; j++) {
            int n = n0 + cn*8 + j;
            float bv = BIAS ? bias[n] : 0.f;
            float* dst = Out + ((size_t)b*N + n)*Mper + p0 + rm*8;
            float4 v0 = {acc[0][j]+bv, acc[1][j]+bv, acc[2][j]+bv, acc[3][j]+bv};
            float4 v1 = {acc[4][j]+bv, acc[5][j]+bv, acc[6][j]+bv, acc[7][j]+bv};
            *(float4*)dst       = v0;
            *((float4*)dst + 1) = v1;
        }
    }
}

// ---------------- attention (flash-style, fp32) ----------------
// Per block: 128 q-rows of one (b,h). K/V streamed in 64-row chunks through smem.
__global__ void __launch_bounds__(128) attn_kernel(const float* __restrict__ Q,
                                                   const float* __restrict__ KV,
                                                   float* __restrict__ AO)
{
    const int b = blockIdx.z, h = blockIdx.y;
    const int p = blockIdx.x * 128 + threadIdx.x;

    __shared__ float Ks[64][64];
    __shared__ float Vs[64][64];

    const float* qp = Q + ((size_t)(b*HW + p)*INNER + h*DH);
    float4 qv[16];
#pragma unroll
    for (int i = 0; i < 16; i++) {
        float4 v = *(const float4*)(qp + i*4);
        v.x *= SCALE; v.y *= SCALE; v.z *= SCALE; v.w *= SCALE;
        qv[i] = v;
    }

    float m = -1e30f, l = 0.f;
    float4 acc[16];
#pragma unroll
    for (int i = 0; i < 16; i++) acc[i] = make_float4(0.f, 0.f, 0.f, 0.f);

    const float* kvb = KV + (size_t)(b*HWK)*(2*INNER) + h*DH;

    for (int ch = 0; ch < 4; ch++) {
        __syncthreads();
#pragma unroll
        for (int r = 0; r < 8; r++) {
            int idx = threadIdx.x + 128*r;       // 0..1023 float4 slots
            int jj = idx >> 4;
            int d4 = idx & 15;
            const float* src = kvb + (size_t)(ch*64 + jj)*(2*INNER) + d4*4;
            *(float4*)&Ks[jj][d4*4] = *(const float4*)src;
            *(float4*)&Vs[jj][d4*4] = *(const float4*)(src + INNER);
        }
        __syncthreads();

        for (int jj = 0; jj < 64; jj++) {
            float4 s4 = make_float4(0.f, 0.f, 0.f, 0.f);
#pragma unroll
            for (int i = 0; i < 16; i++) {
                float4 k4 = *(const float4*)&Ks[jj][i*4];
                s4.x += qv[i].x * k4.x;
                s4.y += qv[i].y * k4.y;
                s4.z += qv[i].z * k4.z;
                s4.w += qv[i].w * k4.w;
            }
            float s = (s4.x + s4.y) + (s4.z + s4.w);

            if (s > m) {   // rare rescale
                float ef = __expf(m - s);
                l *= ef;
#pragma unroll
                for (int i = 0; i < 16; i++) {
                    acc[i].x *= ef; acc[i].y *= ef; acc[i].z *= ef; acc[i].w *= ef;
                }
                m = s;
            }
            float es = __expf(s - m);
            l += es;
#pragma unroll
            for (int i = 0; i < 16; i++) {
                float4 v4 = *(const float4*)&Vs[jj][i*4];
                acc[i].x += es * v4.x;
                acc[i].y += es * v4.y;
                acc[i].z += es * v4.z;
                acc[i].w += es * v4.w;
            }
        }
    }

    float inv = 1.f / l;
    float* op = AO + ((size_t)(b*HW + p)*INNER + h*DH);
#pragma unroll
    for (int i = 0; i < 16; i++) {
        float4 v = acc[i];
        v.x *= inv; v.y *= inv; v.z *= inv; v.w *= inv;
        *(float4*)(op + i*4) = v;
    }
}

// ---------------- launch ----------------
extern "C" void kernel_launch(void* const* d_in, const int* in_sizes, int n_in,
                              void* d_out, int out_size)
{
    const float* x        = (const float*)d_in[0];
    const float* q_dw     = (const float*)d_in[1];
    const float* q_gamma  = (const float*)d_in[2];
    const float* q_beta   = (const float*)d_in[3];
    const float* q_mean   = (const float*)d_in[4];
    const float* q_var    = (const float*)d_in[5];
    const float* q_pw     = (const float*)d_in[6];
    const float* kv_dw    = (const float*)d_in[7];
    const float* kv_gamma = (const float*)d_in[8];
    const float* kv_beta  = (const float*)d_in[9];
    const float* kv_mean  = (const float*)d_in[10];
    const float* kv_var   = (const float*)d_in[11];
    const float* kv_pw    = (const float*)d_in[12];
    const float* out_w    = (const float*)d_in[13];
    const float* out_b    = (const float*)d_in[14];
    float* out = (float*)d_out;

    float *tq, *tkv, *qb, *kvb, *ao;
    cudaGetSymbolAddress((void**)&tq,  g_tq);
    cudaGetSymbolAddress((void**)&tkv, g_tkv);
    cudaGetSymbolAddress((void**)&qb,  g_q);
    cudaGetSymbolAddress((void**)&kvb, g_kv);
    cudaGetSymbolAddress((void**)&ao,  g_ao);

    // 1) depthwise+BN paths
    dwbn_kernel<1, HH, WW, 8> <<<dim3(HH, CC/8,  BN_), 256>>>(x, q_dw,  q_gamma,  q_beta,  q_mean,  q_var,  tq);
    dwbn_kernel<2, HK, WK, 16><<<dim3(HK, CC/16, BN_), 256>>>(x, kv_dw, kv_gamma, kv_beta, kv_mean, kv_var, tkv);

    // 2) pointwise GEMMs
    gemm128<true,  false, false><<<dim3(BN_*HW /128, INNER     /128), 256>>>(tq,  q_pw,  nullptr, qb,  HW,  CC, INNER);
    gemm128<true,  false, false><<<dim3(BN_*HWK/128, (2*INNER) /128), 256>>>(tkv, kv_pw, nullptr, kvb, HWK, CC, 2*INNER);

    // 3) attention
    attn_kernel<<<dim3(HW/128, HEADS, BN_), 128>>>(qb, kvb, ao);

    // 4) final projection (transposed store back to NCHW + bias)
    gemm128<false, true,  true ><<<dim3(BN_*HW/128, CC/128), 256>>>(ao, out_w, out_b, out, HW, INNER, CC);
}

// round 5
// speedup vs baseline: 1.1778x; 1.1201x over previous
#include <cuda_runtime.h>
#include <cstdint>
#include <cstddef>

// ---------------- problem constants ----------------
constexpr int BN_  = 32;    // batch
constexpr int CC   = 384;   // channels
constexpr int HH   = 32, WW = 32, HW = 1024;
constexpr int HK   = 16, WK = 16, HWK = 256;
constexpr int INNER = 384;  // heads*dim
constexpr int HEADS = 6, DH = 64;
constexpr float SCALE = 0.125f;   // 64^-0.5
constexpr float EPS = 1e-5f;

typedef unsigned long long u64;

// ---------------- packed f32x2 helpers (FFMA2 — not emitted by ptxas from C++) ----
__device__ __forceinline__ u64 pack2(float lo, float hi) {
    u64 r; asm("mov.b64 %0, {%1, %2};" : "=l"(r) : "f"(lo), "f"(hi)); return r;
}
__device__ __forceinline__ float2 unpack2(u64 v) {
    float2 f; asm("mov.b64 {%0, %1}, %2;" : "=f"(f.x), "=f"(f.y) : "l"(v)); return f;
}
__device__ __forceinline__ u64 ffma2(u64 a, u64 b, u64 c) {
    u64 d; asm("fma.rn.f32x2 %0, %1, %2, %3;" : "=l"(d) : "l"(a), "l"(b), "l"(c)); return d;
}
__device__ __forceinline__ u64 fmul2(u64 a, u64 b) {
    u64 d; asm("mul.rn.f32x2 %0, %1, %2;" : "=l"(d) : "l"(a), "l"(b)); return d;
}

// ---------------- scratch (device globals; no runtime alloc) ----------------
__device__ float g_tq [(size_t)BN_*CC*HW];        // dwbn(q) output, [b][c][p] (col-major A)
__device__ float g_tkv[(size_t)BN_*CC*HWK];       // dwbn(kv) output
__device__ float g_q  [(size_t)BN_*HW*INNER];     // q, row-major [b*HW+p][inner]
__device__ float g_kv [(size_t)BN_*HWK*2*INNER];  // kv, row-major [b*256+j][768]
__device__ float g_ao [(size_t)BN_*HW*INNER];     // attention out, row-major

// ---------------- depthwise 3x3 conv + BN ----------------
template<int STRIDE, int HO, int WO, int CPB>
__global__ void dwbn_kernel(const float* __restrict__ x, const float* __restrict__ dw,
                            const float* __restrict__ gamma, const float* __restrict__ beta,
                            const float* __restrict__ mean, const float* __restrict__ var,
                            float* __restrict__ out)
{
    const int tid = threadIdx.x;
    const int xo = tid % WO;
    const int cl = tid / WO;
    const int yo = blockIdx.x;
    const int c  = blockIdx.y * CPB + cl;
    const int b  = blockIdx.z;

    const float* xp = x + (size_t)(b*CC + c) * (HH*WW);
    const float* wp = dw + c*9;

    const int yc = yo * STRIDE, xc = xo * STRIDE;
    float s = 0.f;
#pragma unroll
    for (int dy = -1; dy <= 1; dy++) {
        int yy = yc + dy;
        if (yy < 0 || yy >= HH) continue;
#pragma unroll
        for (int dx = -1; dx <= 1; dx++) {
            int xx = xc + dx;
            if (xx < 0 || xx >= WW) continue;
            s += xp[yy*WW + xx] * wp[(dy+1)*3 + (dx+1)];
        }
    }
    float inv = gamma[c] * rsqrtf(var[c] + EPS);
    float val = s * inv + (beta[c] - mean[c]*inv);
    out[(size_t)(b*CC + c) * (HO*WO) + yo*WO + xo] = val;
}

// ---------------- tiled SGEMM (FFMA2 inner product) ----------------
// Out[m][n] = sum_k A(m,k) * Wt[n*K + k]   (Wt row-major [N][K])
// ACOL:  A(m,k) = A[b*K*Mper + k*Mper + p]  with m = b*Mper + p   (per-batch col-major)
// !ACOL: A(m,k) = A[m*K + k]                                      (global row-major)
// TOUT:  store transposed: Out[(b*N + n)*Mper + p]  (+ bias[n] if BIAS)
template<bool ACOL, bool TOUT, bool BIAS>
__global__ void __launch_bounds__(256, 2) gemm128(const float* __restrict__ A,
                                                  const float* __restrict__ Wt,
                                                  const float* __restrict__ bias,
                                                  float* __restrict__ Out,
                                                  int Mper, int K, int N)
{
    constexpr int BM = 128, BNt = 128, BK = 8;
    __shared__ __align__(16) float As[2][BK][BM];
    __shared__ __align__(16) float Bs[2][BK][BNt];

    const int tid = threadIdx.x;
    const int m0  = blockIdx.x * BM;
    const int n0  = blockIdx.y * BNt;
    const int b   = m0 / Mper;      // tiles never straddle batches (Mper % 128 == 0)
    const int p0  = m0 % Mper;

    const float* Abase = ACOL ? (A + (size_t)b*K*Mper + p0)
                              : (A + (size_t)m0 * K);

    const int a_kk = tid >> 5, a_i4 = tid & 31;   // ACOL load map
    const int a_i  = tid >> 1, a_kq = tid & 1;    // row-major load map
    const int b_n  = tid >> 1, b_kq = tid & 1;

    const int rm = tid >> 4;   // 0..15 (row group)
    const int cn = tid & 15;   // 0..15 (col group)

    // acc2[i][jp] holds columns (2*jp, 2*jp+1) for output row i  (packed f32x2)
    u64 acc2[8][4];
#pragma unroll
    for (int i = 0; i < 8; i++)
#pragma unroll
        for (int j = 0; j < 4; j++) acc2[i][j] = 0ull;

    float4 ra, rb;
    auto loadG = [&](int k0) {
        if (ACOL) ra = *(const float4*)(Abase + (size_t)(k0 + a_kk)*Mper + a_i4*4);
        else      ra = *(const float4*)(Abase + (size_t)a_i*K + k0 + a_kq*4);
        rb = *(const float4*)(Wt + (size_t)(n0 + b_n)*K + k0 + b_kq*4);
    };
    auto storeS = [&](int buf) {
        if (ACOL) {
            *(float4*)&As[buf][a_kk][a_i4*4] = ra;
        } else {
            As[buf][a_kq*4+0][a_i] = ra.x;
            As[buf][a_kq*4+1][a_i] = ra.y;
            As[buf][a_kq*4+2][a_i] = ra.z;
            As[buf][a_kq*4+3][a_i] = ra.w;
        }
        Bs[buf][b_kq*4+0][b_n] = rb.x;
        Bs[buf][b_kq*4+1][b_n] = rb.y;
        Bs[buf][b_kq*4+2][b_n] = rb.z;
        Bs[buf][b_kq*4+3][b_n] = rb.w;
    };

    const int T = K / BK;
    loadG(0);
    storeS(0);
    __syncthreads();

    for (int t = 0; t < T; t++) {
        const int buf = t & 1;
        if (t + 1 < T) loadG((t + 1) * BK);
#pragma unroll
        for (int kk = 0; kk < BK; kk++) {
            float a[8];
            *(float4*)&a[0] = *(const float4*)&As[buf][kk][rm*8];
            *(float4*)&a[4] = *(const float4*)&As[buf][kk][rm*8 + 4];
            // column pairs straight from smem as 64-bit words
            ulonglong2 w01 = *(const ulonglong2*)&Bs[buf][kk][cn*8];
            ulonglong2 w23 = *(const ulonglong2*)&Bs[buf][kk][cn*8 + 4];
#pragma unroll
            for (int i = 0; i < 8; i++) {
                u64 aa = pack2(a[i], a[i]);
                acc2[i][0] = ffma2(aa, w01.x, acc2[i][0]);
                acc2[i][1] = ffma2(aa, w01.y, acc2[i][1]);
                acc2[i][2] = ffma2(aa, w23.x, acc2[i][2]);
                acc2[i][3] = ffma2(aa, w23.y, acc2[i][3]);
            }
        }
        if (t + 1 < T) storeS(buf ^ 1);
        __syncthreads();
    }

    if (!TOUT) {
#pragma unroll
        for (int i = 0; i < 8; i++) {
            float2 p0 = unpack2(acc2[i][0]);
            float2 p1 = unpack2(acc2[i][1]);
            float2 p2 = unpack2(acc2[i][2]);
            float2 p3 = unpack2(acc2[i][3]);
            float* dst = Out + (size_t)(m0 + rm*8 + i)*N + n0 + cn*8;
            float4 v0 = {p0.x, p0.y, p1.x, p1.y};
            float4 v1 = {p2.x, p2.y, p3.x, p3.y};
            *(float4*)dst       = v0;
            *((float4*)dst + 1) = v1;
        }
    } else {
#pragma unroll
        for (int jp = 0; jp < 4; jp++) {
            float2 t0[8];
#pragma unroll
            for (int i = 0; i < 8; i++) t0[i] = unpack2(acc2[i][jp]);
#pragma unroll
            for (int half = 0; half < 2; half++) {
                int n = n0 + cn*8 + jp*2 + half;
                float bv = BIAS ? bias[n] : 0.f;
                float* dst = Out + ((size_t)b*N + n)*Mper + p0 + rm*8;
                float c0 = half ? t0[0].y : t0[0].x;
                float c1 = half ? t0[1].y : t0[1].x;
                float c2 = half ? t0[2].y : t0[2].x;
                float c3 = half ? t0[3].y : t0[3].x;
                float c4 = half ? t0[4].y : t0[4].x;
                float c5 = half ? t0[5].y : t0[5].x;
                float c6 = half ? t0[6].y : t0[6].x;
                float c7 = half ? t0[7].y : t0[7].x;
                float4 v0 = {c0+bv, c1+bv, c2+bv, c3+bv};
                float4 v1 = {c4+bv, c5+bv, c6+bv, c7+bv};
                *(float4*)dst       = v0;
                *((float4*)dst + 1) = v1;
            }
        }
    }
}

// ---------------- attention (flash-style, fp32, FFMA2) ----------------
// Per block: 128 q-rows of one (b,h). K/V streamed in 64-row chunks through smem.
__global__ void __launch_bounds__(128) attn_kernel(const float* __restrict__ Q,
                                                   const float* __restrict__ KV,
                                                   float* __restrict__ AO)
{
    const int b = blockIdx.z, h = blockIdx.y;
    const int p = blockIdx.x * 128 + threadIdx.x;

    __shared__ __align__(16) float Ks[64][64];
    __shared__ __align__(16) float Vs[64][64];

    const float* qp = Q + ((size_t)(b*HW + p)*INNER + h*DH);
    // q pre-scaled, packed as 32 f32x2 pairs (dims 2p,2p+1)
    u64 q2[32];
#pragma unroll
    for (int i = 0; i < 16; i++) {
        float4 v = *(const float4*)(qp + i*4);
        q2[2*i]   = pack2(v.x * SCALE, v.y * SCALE);
        q2[2*i+1] = pack2(v.z * SCALE, v.w * SCALE);
    }

    float m = -1e30f, l = 0.f;
    u64 acc2[32];
#pragma unroll
    for (int i = 0; i < 32; i++) acc2[i] = 0ull;

    const float* kvb = KV + (size_t)(b*HWK)*(2*INNER) + h*DH;

    for (int ch = 0; ch < 4; ch++) {
        __syncthreads();
#pragma unroll
        for (int r = 0; r < 8; r++) {
            int idx = threadIdx.x + 128*r;       // 0..1023 float4 slots
            int jj = idx >> 4;
            int d4 = idx & 15;
            const float* src = kvb + (size_t)(ch*64 + jj)*(2*INNER) + d4*4;
            *(float4*)&Ks[jj][d4*4] = *(const float4*)src;
            *(float4*)&Vs[jj][d4*4] = *(const float4*)(src + INNER);
        }
        __syncthreads();

        for (int jj = 0; jj < 64; jj++) {
            const ulonglong2* kp = (const ulonglong2*)&Ks[jj][0];
            u64 s2[4] = {0ull, 0ull, 0ull, 0ull};
#pragma unroll
            for (int i = 0; i < 16; i++) {
                ulonglong2 kk2 = kp[i];
                s2[(2*i)   & 3] = ffma2(q2[2*i],   kk2.x, s2[(2*i)   & 3]);
                s2[(2*i+1) & 3] = ffma2(q2[2*i+1], kk2.y, s2[(2*i+1) & 3]);
            }
            float2 r0 = unpack2(s2[0]), r1 = unpack2(s2[1]);
            float2 r2 = unpack2(s2[2]), r3 = unpack2(s2[3]);
            float s = ((r0.x + r0.y) + (r1.x + r1.y)) + ((r2.x + r2.y) + (r3.x + r3.y));

            if (s > m) {   // rare rescale
                float ef = __expf(m - s);
                l *= ef;
                u64 efp = pack2(ef, ef);
#pragma unroll
                for (int i = 0; i < 32; i++) acc2[i] = fmul2(acc2[i], efp);
                m = s;
            }
            float es = __expf(s - m);
            l += es;
            u64 esp = pack2(es, es);
            const ulonglong2* vp = (const ulonglong2*)&Vs[jj][0];
#pragma unroll
            for (int i = 0; i < 16; i++) {
                ulonglong2 vv = vp[i];
                acc2[2*i]   = ffma2(esp, vv.x, acc2[2*i]);
                acc2[2*i+1] = ffma2(esp, vv.y, acc2[2*i+1]);
            }
        }
    }

    float inv = 1.f / l;
    u64 invp = pack2(inv, inv);
    float* op = AO + ((size_t)(b*HW + p)*INNER + h*DH);
#pragma unroll
    for (int i = 0; i < 16; i++) {
        float2 x0 = unpack2(fmul2(acc2[2*i],   invp));
        float2 x1 = unpack2(fmul2(acc2[2*i+1], invp));
        float4 v = {x0.x, x0.y, x1.x, x1.y};
        *(float4*)(op + i*4) = v;
    }
}

// ---------------- launch ----------------
extern "C" void kernel_launch(void* const* d_in, const int* in_sizes, int n_in,
                              void* d_out, int out_size)
{
    const float* x        = (const float*)d_in[0];
    const float* q_dw     = (const float*)d_in[1];
    const float* q_gamma  = (const float*)d_in[2];
    const float* q_beta   = (const float*)d_in[3];
    const float* q_mean   = (const float*)d_in[4];
    const float* q_var    = (const float*)d_in[5];
    const float* q_pw     = (const float*)d_in[6];
    const float* kv_dw    = (const float*)d_in[7];
    const float* kv_gamma = (const float*)d_in[8];
    const float* kv_beta  = (const float*)d_in[9];
    const float* kv_mean  = (const float*)d_in[10];
    const float* kv_var   = (const float*)d_in[11];
    const float* kv_pw    = (const float*)d_in[12];
    const float* out_w    = (const float*)d_in[13];
    const float* out_b    = (const float*)d_in[14];
    float* out = (float*)d_out;

    float *tq, *tkv, *qb, *kvb, *ao;
    cudaGetSymbolAddress((void**)&tq,  g_tq);
    cudaGetSymbolAddress((void**)&tkv, g_tkv);
    cudaGetSymbolAddress((void**)&qb,  g_q);
    cudaGetSymbolAddress((void**)&kvb, g_kv);
    cudaGetSymbolAddress((void**)&ao,  g_ao);

    // 1) depthwise+BN paths
    dwbn_kernel<1, HH, WW, 8> <<<dim3(HH, CC/8,  BN_), 256>>>(x, q_dw,  q_gamma,  q_beta,  q_mean,  q_var,  tq);
    dwbn_kernel<2, HK, WK, 16><<<dim3(HK, CC/16, BN_), 256>>>(x, kv_dw, kv_gamma, kv_beta, kv_mean, kv_var, tkv);

    // 2) pointwise GEMMs
    gemm128<true,  false, false><<<dim3(BN_*HW /128, INNER     /128), 256>>>(tq,  q_pw,  nullptr, qb,  HW,  CC, INNER);
    gemm128<true,  false, false><<<dim3(BN_*HWK/128, (2*INNER) /128), 256>>>(tkv, kv_pw, nullptr, kvb, HWK, CC, 2*INNER);

    // 3) attention
    attn_kernel<<<dim3(HW/128, HEADS, BN_), 128>>>(qb, kvb, ao);

    // 4) final projection (transposed store back to NCHW + bias)
    gemm128<false, true,  true ><<<dim3(BN_*HW/128, CC/128), 256>>>(ao, out_w, out_b, out, HW, INNER, CC);
}

// round 6
// speedup vs baseline: 1.2121x; 1.0291x over previous
#include <cuda_runtime.h>
#include <cstdint>
#include <cstddef>

// ---------------- problem constants ----------------
constexpr int BN_  = 32;    // batch
constexpr int CC   = 384;   // channels
constexpr int HH   = 32, WW = 32, HW = 1024;
constexpr int HK   = 16, WK = 16, HWK = 256;
constexpr int INNER = 384;  // heads*dim
constexpr int HEADS = 6, DH = 64;
constexpr float SCALE = 0.125f;   // 64^-0.5
constexpr float EPS = 1e-5f;

typedef unsigned long long u64;

// ---------------- packed f32x2 helpers (FFMA2 — not emitted by ptxas from C++) ----
__device__ __forceinline__ u64 pack2(float lo, float hi) {
    u64 r; asm("mov.b64 %0, {%1, %2};" : "=l"(r) : "f"(lo), "f"(hi)); return r;
}
__device__ __forceinline__ float2 unpack2(u64 v) {
    float2 f; asm("mov.b64 {%0, %1}, %2;" : "=f"(f.x), "=f"(f.y) : "l"(v)); return f;
}
__device__ __forceinline__ u64 ffma2(u64 a, u64 b, u64 c) {
    u64 d; asm("fma.rn.f32x2 %0, %1, %2, %3;" : "=l"(d) : "l"(a), "l"(b), "l"(c)); return d;
}
__device__ __forceinline__ u64 fmul2(u64 a, u64 b) {
    u64 d; asm("mul.rn.f32x2 %0, %1, %2;" : "=l"(d) : "l"(a), "l"(b)); return d;
}

// ---------------- scratch (device globals; no runtime alloc) ----------------
__device__ float g_tq [(size_t)BN_*CC*HW];        // dwbn(q) output, [b][c][p] (col-major A)
__device__ float g_tkv[(size_t)BN_*CC*HWK];       // dwbn(kv) output
__device__ float g_q  [(size_t)BN_*HW*INNER];     // q, row-major [b*HW+p][inner]
__device__ float g_kv [(size_t)BN_*HWK*2*INNER];  // kv, row-major [b*256+j][768]
__device__ float g_ao [(size_t)BN_*HW*INNER];     // attention out, row-major

// ---------------- depthwise 3x3 conv + BN ----------------
template<int STRIDE, int HO, int WO, int CPB>
__global__ void dwbn_kernel(const float* __restrict__ x, const float* __restrict__ dw,
                            const float* __restrict__ gamma, const float* __restrict__ beta,
                            const float* __restrict__ mean, const float* __restrict__ var,
                            float* __restrict__ out)
{
    const int tid = threadIdx.x;
    const int xo = tid % WO;
    const int cl = tid / WO;
    const int yo = blockIdx.x;
    const int c  = blockIdx.y * CPB + cl;
    const int b  = blockIdx.z;

    const float* xp = x + (size_t)(b*CC + c) * (HH*WW);
    const float* wp = dw + c*9;

    const int yc = yo * STRIDE, xc = xo * STRIDE;
    float s = 0.f;
#pragma unroll
    for (int dy = -1; dy <= 1; dy++) {
        int yy = yc + dy;
        if (yy < 0 || yy >= HH) continue;
#pragma unroll
        for (int dx = -1; dx <= 1; dx++) {
            int xx = xc + dx;
            if (xx < 0 || xx >= WW) continue;
            s += xp[yy*WW + xx] * wp[(dy+1)*3 + (dx+1)];
        }
    }
    float inv = gamma[c] * rsqrtf(var[c] + EPS);
    float val = s * inv + (beta[c] - mean[c]*inv);
    out[(size_t)(b*CC + c) * (HO*WO) + yo*WO + xo] = val;
}

// ---------------- tiled SGEMM (FFMA2 inner product) ----------------
template<bool ACOL, bool TOUT, bool BIAS>
__global__ void __launch_bounds__(256, 2) gemm128(const float* __restrict__ A,
                                                  const float* __restrict__ Wt,
                                                  const float* __restrict__ bias,
                                                  float* __restrict__ Out,
                                                  int Mper, int K, int N)
{
    constexpr int BM = 128, BNt = 128, BK = 8;
    __shared__ __align__(16) float As[2][BK][BM];
    __shared__ __align__(16) float Bs[2][BK][BNt];

    const int tid = threadIdx.x;
    const int m0  = blockIdx.x * BM;
    const int n0  = blockIdx.y * BNt;
    const int b   = m0 / Mper;
    const int p0  = m0 % Mper;

    const float* Abase = ACOL ? (A + (size_t)b*K*Mper + p0)
                              : (A + (size_t)m0 * K);

    const int a_kk = tid >> 5, a_i4 = tid & 31;
    const int a_i  = tid >> 1, a_kq = tid & 1;
    const int b_n  = tid >> 1, b_kq = tid & 1;

    const int rm = tid >> 4;
    const int cn = tid & 15;

    u64 acc2[8][4];
#pragma unroll
    for (int i = 0; i < 8; i++)
#pragma unroll
        for (int j = 0; j < 4; j++) acc2[i][j] = 0ull;

    float4 ra, rb;
    auto loadG = [&](int k0) {
        if (ACOL) ra = *(const float4*)(Abase + (size_t)(k0 + a_kk)*Mper + a_i4*4);
        else      ra = *(const float4*)(Abase + (size_t)a_i*K + k0 + a_kq*4);
        rb = *(const float4*)(Wt + (size_t)(n0 + b_n)*K + k0 + b_kq*4);
    };
    auto storeS = [&](int buf) {
        if (ACOL) {
            *(float4*)&As[buf][a_kk][a_i4*4] = ra;
        } else {
            As[buf][a_kq*4+0][a_i] = ra.x;
            As[buf][a_kq*4+1][a_i] = ra.y;
            As[buf][a_kq*4+2][a_i] = ra.z;
            As[buf][a_kq*4+3][a_i] = ra.w;
        }
        Bs[buf][b_kq*4+0][b_n] = rb.x;
        Bs[buf][b_kq*4+1][b_n] = rb.y;
        Bs[buf][b_kq*4+2][b_n] = rb.z;
        Bs[buf][b_kq*4+3][b_n] = rb.w;
    };

    const int T = K / BK;
    loadG(0);
    storeS(0);
    __syncthreads();

    for (int t = 0; t < T; t++) {
        const int buf = t & 1;
        if (t + 1 < T) loadG((t + 1) * BK);
#pragma unroll
        for (int kk = 0; kk < BK; kk++) {
            float a[8];
            *(float4*)&a[0] = *(const float4*)&As[buf][kk][rm*8];
            *(float4*)&a[4] = *(const float4*)&As[buf][kk][rm*8 + 4];
            ulonglong2 w01 = *(const ulonglong2*)&Bs[buf][kk][cn*8];
            ulonglong2 w23 = *(const ulonglong2*)&Bs[buf][kk][cn*8 + 4];
#pragma unroll
            for (int i = 0; i < 8; i++) {
                u64 aa = pack2(a[i], a[i]);
                acc2[i][0] = ffma2(aa, w01.x, acc2[i][0]);
                acc2[i][1] = ffma2(aa, w01.y, acc2[i][1]);
                acc2[i][2] = ffma2(aa, w23.x, acc2[i][2]);
                acc2[i][3] = ffma2(aa, w23.y, acc2[i][3]);
            }
        }
        if (t + 1 < T) storeS(buf ^ 1);
        __syncthreads();
    }

    if (!TOUT) {
#pragma unroll
        for (int i = 0; i < 8; i++) {
            float2 p0v = unpack2(acc2[i][0]);
            float2 p1v = unpack2(acc2[i][1]);
            float2 p2v = unpack2(acc2[i][2]);
            float2 p3v = unpack2(acc2[i][3]);
            float* dst = Out + (size_t)(m0 + rm*8 + i)*N + n0 + cn*8;
            float4 v0 = {p0v.x, p0v.y, p1v.x, p1v.y};
            float4 v1 = {p2v.x, p2v.y, p3v.x, p3v.y};
            *(float4*)dst       = v0;
            *((float4*)dst + 1) = v1;
        }
    } else {
#pragma unroll
        for (int jp = 0; jp < 4; jp++) {
            float2 t0[8];
#pragma unroll
            for (int i = 0; i < 8; i++) t0[i] = unpack2(acc2[i][jp]);
#pragma unroll
            for (int half = 0; half < 2; half++) {
                int n = n0 + cn*8 + jp*2 + half;
                float bv = BIAS ? bias[n] : 0.f;
                float* dst = Out + ((size_t)b*N + n)*Mper + p0 + rm*8;
                float c0 = half ? t0[0].y : t0[0].x;
                float c1 = half ? t0[1].y : t0[1].x;
                float c2 = half ? t0[2].y : t0[2].x;
                float c3 = half ? t0[3].y : t0[3].x;
                float c4 = half ? t0[4].y : t0[4].x;
                float c5 = half ? t0[5].y : t0[5].x;
                float c6 = half ? t0[6].y : t0[6].x;
                float c7 = half ? t0[7].y : t0[7].x;
                float4 v0 = {c0+bv, c1+bv, c2+bv, c3+bv};
                float4 v1 = {c4+bv, c5+bv, c6+bv, c7+bv};
                *(float4*)dst       = v0;
                *((float4*)dst + 1) = v1;
            }
        }
    }
}

// ---------------- attention: GEMM-ified, one block per (b, h, 128 q-rows) ----------------
// 512 threads. Phase A: S = (Q*SCALE) K^T via register-tiled GEMM (warp tile 32x64,
// thread tile 8x8, FFMA2). Exact two-pass softmax (warp shfl + tiny cross-warp smem).
// P stored row-pair-packed (u64) so Phase B (O = P V) reads P via broadcast LDS.128.
// 1/l normalization deferred to the final store.
//
// dynamic smem layout (floats):
//   As  [128][65]            @ 0       (8320)   -- Q, padded for conflict-free broadcast
//   Bs  [2][8][256]          @ 8320    (4096)   -- K k-slices, double buffered
//   Ps2 [256][66] (u64)      @ 12416   (33792)  -- P, row-pairs packed
//   aliases inside As region after phase A:
//   redmax[128][4] @ 0, redsum[128][4] @ 512, linv[128] @ 1024, Vs[32][64] @ 1280
constexpr int ATTN_SMEM_FLOATS = 12416 + 33792;
constexpr size_t ATTN_SMEM_BYTES = (size_t)ATTN_SMEM_FLOATS * 4;   // 184832

__global__ void __launch_bounds__(512, 1)
attn_kernel(const float* __restrict__ Q, const float* __restrict__ KV,
            float* __restrict__ AO)
{
    extern __shared__ float sm[];
    float* As      = sm;                    // [128][65]
    float* Bs      = sm + 8320;             // [2][8][256]
    u64*   Ps2     = (u64*)(sm + 12416);    // [256][66] u64
    float* redmax  = sm;                    // alias of As (safe after phase A)
    float* redsum  = sm + 512;
    float* linv_sm = sm + 1024;
    float* Vs      = sm + 1280;             // [32][64]

    const int tid  = threadIdx.x;
    const int w    = tid >> 5, lane = tid & 31;
    const int b    = blockIdx.z, h = blockIdx.y;
    const int m0   = blockIdx.x * 128;

    const float* qbase = Q  + ((size_t)(b*HW + m0))*INNER + h*DH;
    const float* kvK   = KV + (size_t)b*HWK*(2*INNER) + h*DH;
    const float* kvV   = kvK + INNER;

    // ---- load Q tile into As [m][d], pad 65, pre-scaled ----
#pragma unroll
    for (int r = 0; r < 4; r++) {
        int slot = tid + 512*r;             // 0..2047 float4 slots
        int m = slot >> 4, d4 = slot & 15;
        float4 v = *(const float4*)(qbase + (size_t)m*INNER + d4*4);
        float* dst = As + m*65 + d4*4;
        dst[0] = v.x*SCALE; dst[1] = v.y*SCALE; dst[2] = v.z*SCALE; dst[3] = v.w*SCALE;
    }

    // ---- Bs slice loader (K^T slices: Bs[kk][n]) ----
    const int bn = tid >> 1, bd4 = tid & 1;
    float4 rbv;
    auto loadB = [&](int t) {
        rbv = *(const float4*)(kvK + (size_t)bn*(2*INNER) + t*8 + bd4*4);
    };
    auto storeB = [&](int buf) {
        float* base = Bs + buf*(8*256);
        base[(bd4*4+0)*256 + bn] = rbv.x;
        base[(bd4*4+1)*256 + bn] = rbv.y;
        base[(bd4*4+2)*256 + bn] = rbv.z;
        base[(bd4*4+3)*256 + bn] = rbv.w;
    };

    loadB(0); storeB(0);
    __syncthreads();

    // warp/lane tiling: warp grid 4x4 (wr rows, wc cols); lane grid 4x8 (lr, lc)
    const int wr = w >> 2, wc = w & 3;
    const int lr = lane >> 3, lc = lane & 7;
    const int mrow = wr*32 + lr*8;          // thread's first q-row (0..127)
    const int ncol = wc*64 + lc*8;          // thread's first key   (0..255)

    // ---- phase A: S = Q K^T  (acc2[i][jp] = keys 2jp,2jp+1 of row i) ----
    u64 acc2[8][4];
#pragma unroll
    for (int i = 0; i < 8; i++)
#pragma unroll
        for (int j = 0; j < 4; j++) acc2[i][j] = 0ull;

    for (int t = 0; t < 8; t++) {
        const int buf = t & 1;
        if (t < 7) loadB(t+1);
        const float* bbase = Bs + buf*(8*256) + ncol;
        const float* abase = As + mrow*65 + t*8;
#pragma unroll
        for (int kk = 0; kk < 8; kk++) {
            ulonglong2 w01 = *(const ulonglong2*)(bbase + kk*256);
            ulonglong2 w23 = *(const ulonglong2*)(bbase + kk*256 + 4);
#pragma unroll
            for (int i = 0; i < 8; i++) {
                float av = abase[i*65 + kk];
                u64 aa = pack2(av, av);
                acc2[i][0] = ffma2(aa, w01.x, acc2[i][0]);
                acc2[i][1] = ffma2(aa, w01.y, acc2[i][1]);
                acc2[i][2] = ffma2(aa, w23.x, acc2[i][2]);
                acc2[i][3] = ffma2(aa, w23.y, acc2[i][3]);
            }
        }
        if (t < 7) storeB(buf ^ 1);
        __syncthreads();   // final iteration's sync also makes As-alias writes safe
    }

    // ---- softmax pass 1: row maxima ----
    float rmax[8];
#pragma unroll
    for (int i = 0; i < 8; i++) {
        float2 x0 = unpack2(acc2[i][0]);
        float2 x1 = unpack2(acc2[i][1]);
        float2 x2 = unpack2(acc2[i][2]);
        float2 x3 = unpack2(acc2[i][3]);
        rmax[i] = fmaxf(fmaxf(fmaxf(x0.x,x0.y), fmaxf(x1.x,x1.y)),
                        fmaxf(fmaxf(x2.x,x2.y), fmaxf(x3.x,x3.y)));
    }
#pragma unroll
    for (int i = 0; i < 8; i++) {
        rmax[i] = fmaxf(rmax[i], __shfl_xor_sync(0xffffffffu, rmax[i], 1));
        rmax[i] = fmaxf(rmax[i], __shfl_xor_sync(0xffffffffu, rmax[i], 2));
        rmax[i] = fmaxf(rmax[i], __shfl_xor_sync(0xffffffffu, rmax[i], 4));
    }
    if (lc == 0) {
#pragma unroll
        for (int i = 0; i < 8; i++) redmax[(mrow+i)*4 + wc] = rmax[i];
    }
    __syncthreads();
#pragma unroll
    for (int i = 0; i < 8; i++) {
        const float* rp = redmax + (mrow+i)*4;
        rmax[i] = fmaxf(fmaxf(rp[0], rp[1]), fmaxf(rp[2], rp[3]));
    }

    // ---- softmax pass 2: exp, store packed P (unnormalized), row sums ----
    float lsum[8];
    const int r2base = mrow >> 1;
#pragma unroll
    for (int ip = 0; ip < 4; ip++) {
        const int i0 = 2*ip, i1 = 2*ip+1;
        float e0[8], e1[8];
        {
            float2 x0 = unpack2(acc2[i0][0]), x1 = unpack2(acc2[i0][1]);
            float2 x2 = unpack2(acc2[i0][2]), x3 = unpack2(acc2[i0][3]);
            e0[0]=__expf(x0.x-rmax[i0]); e0[1]=__expf(x0.y-rmax[i0]);
            e0[2]=__expf(x1.x-rmax[i0]); e0[3]=__expf(x1.y-rmax[i0]);
            e0[4]=__expf(x2.x-rmax[i0]); e0[5]=__expf(x2.y-rmax[i0]);
            e0[6]=__expf(x3.x-rmax[i0]); e0[7]=__expf(x3.y-rmax[i0]);
        }
        {
            float2 x0 = unpack2(acc2[i1][0]), x1 = unpack2(acc2[i1][1]);
            float2 x2 = unpack2(acc2[i1][2]), x3 = unpack2(acc2[i1][3]);
            e1[0]=__expf(x0.x-rmax[i1]); e1[1]=__expf(x0.y-rmax[i1]);
            e1[2]=__expf(x1.x-rmax[i1]); e1[3]=__expf(x1.y-rmax[i1]);
            e1[4]=__expf(x2.x-rmax[i1]); e1[5]=__expf(x2.y-rmax[i1]);
            e1[6]=__expf(x3.x-rmax[i1]); e1[7]=__expf(x3.y-rmax[i1]);
        }
        float s0 = 0.f, s1 = 0.f;
#pragma unroll
        for (int j = 0; j < 8; j++) { s0 += e0[j]; s1 += e1[j]; }
        lsum[i0] = s0; lsum[i1] = s1;
#pragma unroll
        for (int j = 0; j < 8; j++)
            Ps2[(size_t)(ncol+j)*66 + r2base + ip] = pack2(e0[j], e1[j]);
    }
#pragma unroll
    for (int i = 0; i < 8; i++) {
        lsum[i] += __shfl_xor_sync(0xffffffffu, lsum[i], 1);
        lsum[i] += __shfl_xor_sync(0xffffffffu, lsum[i], 2);
        lsum[i] += __shfl_xor_sync(0xffffffffu, lsum[i], 4);
    }
    if (lc == 0) {
#pragma unroll
        for (int i = 0; i < 8; i++) redsum[(mrow+i)*4 + wc] = lsum[i];
    }
    __syncthreads();
    if (lc == 0 && wc == 0) {
#pragma unroll
        for (int i = 0; i < 8; i++) {
            const float* rp = redsum + (mrow+i)*4;
            linv_sm[mrow+i] = 1.f / (rp[0] + rp[1] + rp[2] + rp[3]);
        }
    }

    // ---- phase B: O = P V  (oacc[ip][d] lanes = rows 2ip, 2ip+1; d = dim pair) ----
    u64 oacc[4][2];
#pragma unroll
    for (int ip = 0; ip < 4; ip++) { oacc[ip][0] = 0ull; oacc[ip][1] = 0ull; }

    const int rm2 = w;            // rows rm2*8 .. rm2*8+7
    const int d0  = lane * 2;     // dims d0, d0+1

    for (int ch = 0; ch < 8; ch++) {
        __syncthreads();          // first one also publishes Ps2/linv; later ones protect Vs
        {
            int r = tid >> 4, d4 = tid & 15;
            *(float4*)&Vs[r*64 + d4*4] =
                *(const float4*)(kvV + (size_t)(ch*32 + r)*(2*INNER) + d4*4);
        }
        __syncthreads();
#pragma unroll 4
        for (int kk2 = 0; kk2 < 32; kk2++) {
            const int kk = ch*32 + kk2;
            const u64* pb = Ps2 + (size_t)kk*66 + rm2*4;
            ulonglong2 p01 = *(const ulonglong2*)pb;         // rowpairs 0,1 (rows 0..3)
            ulonglong2 p23 = *(const ulonglong2*)(pb + 2);   // rowpairs 2,3 (rows 4..7)
            float2 vf = *(const float2*)&Vs[kk2*64 + d0];
            u64 vx = pack2(vf.x, vf.x);
            u64 vy = pack2(vf.y, vf.y);
            oacc[0][0] = ffma2(p01.x, vx, oacc[0][0]);
            oacc[0][1] = ffma2(p01.x, vy, oacc[0][1]);
            oacc[1][0] = ffma2(p01.y, vx, oacc[1][0]);
            oacc[1][1] = ffma2(p01.y, vy, oacc[1][1]);
            oacc[2][0] = ffma2(p23.x, vx, oacc[2][0]);
            oacc[2][1] = ffma2(p23.x, vy, oacc[2][1]);
            oacc[3][0] = ffma2(p23.y, vx, oacc[3][0]);
            oacc[3][1] = ffma2(p23.y, vy, oacc[3][1]);
        }
    }

    // ---- normalize by 1/l and store ----
    float* aobase = AO + ((size_t)(b*HW + m0 + rm2*8))*INNER + h*DH + d0;
#pragma unroll
    for (int ip = 0; ip < 4; ip++) {
        float2 lv = *(const float2*)&linv_sm[rm2*8 + 2*ip];
        u64 lp = pack2(lv.x, lv.y);
        float2 o0 = unpack2(fmul2(oacc[ip][0], lp));   // dim d0   : rows 2ip, 2ip+1
        float2 o1 = unpack2(fmul2(oacc[ip][1], lp));   // dim d0+1 : rows 2ip, 2ip+1
        *(float2*)(aobase + (size_t)(2*ip)  *INNER) = make_float2(o0.x, o1.x);
        *(float2*)(aobase + (size_t)(2*ip+1)*INNER) = make_float2(o0.y, o1.y);
    }
}

// ---------------- launch ----------------
extern "C" void kernel_launch(void* const* d_in, const int* in_sizes, int n_in,
                              void* d_out, int out_size)
{
    const float* x        = (const float*)d_in[0];
    const float* q_dw     = (const float*)d_in[1];
    const float* q_gamma  = (const float*)d_in[2];
    const float* q_beta   = (const float*)d_in[3];
    const float* q_mean   = (const float*)d_in[4];
    const float* q_var    = (const float*)d_in[5];
    const float* q_pw     = (const float*)d_in[6];
    const float* kv_dw    = (const float*)d_in[7];
    const float* kv_gamma = (const float*)d_in[8];
    const float* kv_beta  = (const float*)d_in[9];
    const float* kv_mean  = (const float*)d_in[10];
    const float* kv_var   = (const float*)d_in[11];
    const float* kv_pw    = (const float*)d_in[12];
    const float* out_w    = (const float*)d_in[13];
    const float* out_b    = (const float*)d_in[14];
    float* out = (float*)d_out;

    float *tq, *tkv, *qb, *kvb, *ao;
    cudaGetSymbolAddress((void**)&tq,  g_tq);
    cudaGetSymbolAddress((void**)&tkv, g_tkv);
    cudaGetSymbolAddress((void**)&qb,  g_q);
    cudaGetSymbolAddress((void**)&kvb, g_kv);
    cudaGetSymbolAddress((void**)&ao,  g_ao);

    static bool attr_set = false;
    if (!attr_set) {
        cudaFuncSetAttribute(attn_kernel,
                             cudaFuncAttributeMaxDynamicSharedMemorySize,
                             (int)ATTN_SMEM_BYTES);
        attr_set = true;
    }

    // 1) depthwise+BN paths
    dwbn_kernel<1, HH, WW, 8> <<<dim3(HH, CC/8,  BN_), 256>>>(x, q_dw,  q_gamma,  q_beta,  q_mean,  q_var,  tq);
    dwbn_kernel<2, HK, WK, 16><<<dim3(HK, CC/16, BN_), 256>>>(x, kv_dw, kv_gamma, kv_beta, kv_mean, kv_var, tkv);

    // 2) pointwise GEMMs
    gemm128<true,  false, false><<<dim3(BN_*HW /128, INNER     /128), 256>>>(tq,  q_pw,  nullptr, qb,  HW,  CC, INNER);
    gemm128<true,  false, false><<<dim3(BN_*HWK/128, (2*INNER) /128), 256>>>(tkv, kv_pw, nullptr, kvb, HWK, CC, 2*INNER);

    // 3) attention (GEMM-ified, fused softmax)
    attn_kernel<<<dim3(HW/128, HEADS, BN_), 512, ATTN_SMEM_BYTES>>>(qb, kvb, ao);

    // 4) final projection (transposed store back to NCHW + bias)
    gemm128<false, true,  true ><<<dim3(BN_*HW/128, CC/128), 256>>>(ao, out_w, out_b, out, HW, INNER, CC);
}